// round 5
// baseline (speedup 1.0000x reference)
#include <cuda_runtime.h>
#include <cuda_bf16.h>
#include <cstdint>

#define NROW 8192
#define DDIM 1024
#define CHB 128                   // K bytes per chunk row (128 int8 = K128)
#define KCH (DDIM / CHB)          // 8 chunks
#define STAGES 3
#define TM 128                    // CTA tile M
#define TN 256                    // CTA tile N
#define NTM (NROW / TM)           // 64
#define NTN (NROW / TN)           // 32
#define STG_A (TM * CHB)          // 16 KB
#define STG_B (TN * CHB)          // 32 KB
#define STG_BYTES (STG_A + STG_B) // 48 KB
#define CHUNK_STRIDE ((size_t)NROW * CHB)  // 1 MB per k-chunk blob
#define MARGINF 1.0f

// ---------------- device scratch ----------------
__device__ int8_t g_imgq[(size_t)NROW * DDIM];   // chunk-major swizzled, 8 MB
__device__ int8_t g_txtq[(size_t)NROW * DDIM];   // chunk-major swizzled, 8 MB
__device__ float g_sclI[NROW];                   // per-row dequant scales
__device__ float g_sclT[NROW];
__device__ float g_pos[NROW];
__device__ float g_partial[(size_t)NTN * NROW];  // [ntile][row]
__device__ float g_lse[NROW];

// ---------------- PTX helpers ----------------
__device__ __forceinline__ uint32_t smem_u32(const void* p) {
    uint32_t a;
    asm("{ .reg .u64 t; cvta.to.shared.u64 t, %1; cvt.u32.u64 %0, t; }" : "=r"(a) : "l"(p));
    return a;
}
__device__ __forceinline__ void mbar_init(uint32_t a, uint32_t c) {
    asm volatile("mbarrier.init.shared.b64 [%0], %1;" :: "r"(a), "r"(c) : "memory");
}
__device__ __forceinline__ void mbar_inval(uint32_t a) {
    asm volatile("mbarrier.inval.shared.b64 [%0];" :: "r"(a) : "memory");
}
__device__ __forceinline__ void mbar_expect_tx(uint32_t a, uint32_t tx) {
    asm volatile("mbarrier.arrive.expect_tx.shared.b64 _, [%0], %1;" :: "r"(a), "r"(tx) : "memory");
}
__device__ __forceinline__ void mbar_wait(uint32_t a, uint32_t parity) {
    asm volatile(
        "{\n\t.reg .pred P;\n\t"
        "WL_%=:\n\t"
        "mbarrier.try_wait.parity.shared.b64 P, [%0], %1;\n\t"
        "@!P bra WL_%=;\n\t}"
        :: "r"(a), "r"(parity) : "memory");
}
__device__ __forceinline__ void bulk_g2s(uint32_t dst, const void* src, uint32_t bytes, uint32_t mbar) {
    asm volatile(
        "cp.async.bulk.shared::cluster.global.mbarrier::complete_tx::bytes [%0], [%1], %2, [%3];"
        :: "r"(dst), "l"(src), "r"(bytes), "r"(mbar) : "memory");
}
__device__ __forceinline__ void ldsm_x4(uint32_t& r0, uint32_t& r1, uint32_t& r2, uint32_t& r3,
                                        uint32_t addr) {
    asm volatile("ldmatrix.sync.aligned.m8n8.x4.shared.b16 {%0,%1,%2,%3}, [%4];"
                 : "=r"(r0), "=r"(r1), "=r"(r2), "=r"(r3) : "r"(addr));
}
__device__ __forceinline__ void mma_s8(int& c0, int& c1, int& c2, int& c3,
                                       uint32_t a0, uint32_t a1, uint32_t a2, uint32_t a3,
                                       uint32_t b0, uint32_t b1) {
    asm volatile(
        "mma.sync.aligned.m16n8k32.row.col.s32.s8.s8.s32 "
        "{%0,%1,%2,%3}, {%4,%5,%6,%7}, {%8,%9}, {%0,%1,%2,%3};"
        : "+r"(c0), "+r"(c1), "+r"(c2), "+r"(c3)
        : "r"(a0), "r"(a1), "r"(a2), "r"(a3), "r"(b0), "r"(b1));
}
__device__ __forceinline__ int8_t q8(float x, float qs) {
    int v = __float2int_rn(x * qs);
    v = max(-127, min(127, v));
    return (int8_t)v;
}

// ---------------------------------------------------------------------------
// Kernel 1: L2-normalize -> int8 per-row-scaled, chunk-major + XOR-swizzled;
// exact fp32 positives; per-row dequant scales.
// byte addr = chunk*CHUNK_STRIDE + row*128 + col_in_chunk, off ^= (off>>3)&0x70
// ---------------------------------------------------------------------------
__global__ void norm_kernel(const float* __restrict__ img,
                            const float* __restrict__ txt) {
    const int row = blockIdx.x;
    const int t = threadIdx.x;

    const float4 a = reinterpret_cast<const float4*>(img + (size_t)row * DDIM)[t];
    const float4 b = reinterpret_cast<const float4*>(txt + (size_t)row * DDIM)[t];

    float sii = a.x * a.x + a.y * a.y + a.z * a.z + a.w * a.w;
    float stt = b.x * b.x + b.y * b.y + b.z * b.z + b.w * b.w;
    float sit = a.x * b.x + a.y * b.y + a.z * b.z + a.w * b.w;
    float ma = fmaxf(fmaxf(fabsf(a.x), fabsf(a.y)), fmaxf(fabsf(a.z), fabsf(a.w)));
    float mb = fmaxf(fmaxf(fabsf(b.x), fabsf(b.y)), fmaxf(fabsf(b.z), fabsf(b.w)));

    #pragma unroll
    for (int o = 16; o; o >>= 1) {
        sii += __shfl_xor_sync(0xffffffffu, sii, o);
        stt += __shfl_xor_sync(0xffffffffu, stt, o);
        sit += __shfl_xor_sync(0xffffffffu, sit, o);
        ma = fmaxf(ma, __shfl_xor_sync(0xffffffffu, ma, o));
        mb = fmaxf(mb, __shfl_xor_sync(0xffffffffu, mb, o));
    }

    __shared__ float w0[8], w1[8], w2[8], w3[8], w4[8], bc[5];
    if ((t & 31) == 0) {
        w0[t >> 5] = sii; w1[t >> 5] = stt; w2[t >> 5] = sit;
        w3[t >> 5] = ma;  w4[t >> 5] = mb;
    }
    __syncthreads();
    if (t == 0) {
        float a0 = 0.f, a1 = 0.f, a2 = 0.f, a3 = 0.f, a4 = 0.f;
        #pragma unroll
        for (int i = 0; i < 8; i++) {
            a0 += w0[i]; a1 += w1[i]; a2 += w2[i];
            a3 = fmaxf(a3, w3[i]); a4 = fmaxf(a4, w4[i]);
        }
        bc[0] = a0; bc[1] = a1; bc[2] = a2; bc[3] = a3; bc[4] = a4;
    }
    __syncthreads();

    const float inv_i = 1.0f / fmaxf(sqrtf(bc[0]), 1e-12f);
    const float inv_t = 1.0f / fmaxf(sqrtf(bc[1]), 1e-12f);
    const float mni = fmaxf(bc[3] * inv_i, 1e-12f);   // maxabs of normalized img row
    const float mnt = fmaxf(bc[4] * inv_t, 1e-12f);
    const float qsi = 127.0f / mni;                    // quant scale (applied post-normalize)
    const float qst = 127.0f / mnt;

    char4 qa, qb;
    qa.x = q8(a.x * inv_i, qsi); qa.y = q8(a.y * inv_i, qsi);
    qa.z = q8(a.z * inv_i, qsi); qa.w = q8(a.w * inv_i, qsi);
    qb.x = q8(b.x * inv_t, qst); qb.y = q8(b.y * inv_t, qst);
    qb.z = q8(b.z * inv_t, qst); qb.w = q8(b.w * inv_t, qst);

    const int c = t >> 5;                 // k-chunk (128 int8 each)
    const int ci = (t & 31) << 2;         // byte within chunk row
    uint32_t off = (uint32_t)row * 128u + (uint32_t)ci;
    off ^= (off >> 3) & 0x70u;            // 4B granule within 16B unit: safe
    const size_t addr = (size_t)c * CHUNK_STRIDE + off;

    *reinterpret_cast<char4*>(reinterpret_cast<char*>(g_imgq) + addr) = qa;
    *reinterpret_cast<char4*>(reinterpret_cast<char*>(g_txtq) + addr) = qb;

    if (t == 0) {
        g_pos[row] = bc[2] * inv_i * inv_t;     // exact fp32 diagonal
        g_sclI[row] = mni * (1.0f / 127.0f);    // dequant scales
        g_sclT[row] = mnt * (1.0f / 127.0f);
    }
}

// ---------------------------------------------------------------------------
// Kernel 2: bulk-async pipelined IMMA s8 GEMM (s32 acc) + fused exp rowsum.
// CTA tile 128x256, 8 warps = 2(m) x 4(n), warp tile 64x64. K=128 per chunk.
// ---------------------------------------------------------------------------
__global__ __launch_bounds__(256, 1) void gemm_lse_kernel() {
    extern __shared__ __align__(128) char smem[];       // STAGES*48KB (+pad)
    __shared__ __align__(8) unsigned long long full_bar[STAGES];
    __shared__ float rowAcc[TM];

    const int tid = threadIdx.x;
    const int warp = tid >> 5;
    const int lane = tid & 31;
    const int wm = warp >> 2;        // 0..1
    const int wn = warp & 3;         // 0..3
    const int mtile = blockIdx.x;    // 64
    const int ntile = blockIdx.y;    // 32

    uint32_t sbase = smem_u32(smem);
    sbase = (sbase + 127u) & ~127u;
    const uint32_t fullb = smem_u32(&full_bar[0]);

    if (tid == 0) {
        #pragma unroll
        for (int s = 0; s < STAGES; s++) mbar_init(fullb + 8u * s, 1);
    }
    if (tid < TM) rowAcc[tid] = 0.0f;
    __syncthreads();

    const char* baseA = reinterpret_cast<const char*>(g_imgq) + (size_t)mtile * STG_A;
    const char* baseB = reinterpret_cast<const char*>(g_txtq) + (size_t)ntile * STG_B;

    if (tid == 0) {
        #pragma unroll
        for (int c = 0; c < STAGES - 1; c++) {
            const uint32_t st = sbase + (uint32_t)c * STG_BYTES;
            mbar_expect_tx(fullb + 8u * c, STG_BYTES);
            bulk_g2s(st,         baseA + (size_t)c * CHUNK_STRIDE, STG_A, fullb + 8u * c);
            bulk_g2s(st + STG_A, baseB + (size_t)c * CHUNK_STRIDE, STG_B, fullb + 8u * c);
        }
    }

    int acc[4][8][4];
    #pragma unroll
    for (int mi = 0; mi < 4; mi++)
        #pragma unroll
        for (int ni = 0; ni < 8; ni++)
            #pragma unroll
            for (int e = 0; e < 4; e++) acc[mi][ni][e] = 0;

    for (int c = 0; c < KCH; c++) {
        const int s = c % STAGES;
        mbar_wait(fullb + 8u * s, (uint32_t)((c / STAGES) & 1));
        __syncthreads();   // all warps done with slot (c-1)%STAGES -> reusable

        if (tid == 0) {
            const int nx = c + STAGES - 1;
            if (nx < KCH) {
                const int sn = nx % STAGES;
                const uint32_t st = sbase + (uint32_t)sn * STG_BYTES;
                mbar_expect_tx(fullb + 8u * sn, STG_BYTES);
                bulk_g2s(st,         baseA + (size_t)nx * CHUNK_STRIDE, STG_A, fullb + 8u * sn);
                bulk_g2s(st + STG_A, baseB + (size_t)nx * CHUNK_STRIDE, STG_B, fullb + 8u * sn);
            }
        }

        const uint32_t sa = sbase + (uint32_t)s * STG_BYTES;
        const uint32_t sb = sa + STG_A;

        #pragma unroll
        for (int ks = 0; ks < 4; ks++) {          // 4 x k32 = K128
            uint32_t a[4][4], b[4][4];
            #pragma unroll
            for (int mi = 0; mi < 4; mi++) {
                const int r = wm * 64 + mi * 16 + (lane & 15);
                const int g = 2 * ks + (lane >> 4);      // 16B group (0..7)
                ldsm_x4(a[mi][0], a[mi][1], a[mi][2], a[mi][3],
                        sa + (uint32_t)r * 128u + (uint32_t)((g ^ (r & 7)) << 4));
            }
            #pragma unroll
            for (int bi = 0; bi < 4; bi++) {
                const int nr = wn * 64 + bi * 16 + (lane & 7) + ((lane >> 4) << 3);
                const int g = 2 * ks + ((lane >> 3) & 1);
                ldsm_x4(b[bi][0], b[bi][1], b[bi][2], b[bi][3],
                        sb + (uint32_t)nr * 128u + (uint32_t)((g ^ (nr & 7)) << 4));
            }
            #pragma unroll
            for (int mi = 0; mi < 4; mi++)
                #pragma unroll
                for (int ni = 0; ni < 8; ni++)
                    mma_s8(acc[mi][ni][0], acc[mi][ni][1], acc[mi][ni][2], acc[mi][ni][3],
                           a[mi][0], a[mi][1], a[mi][2], a[mi][3],
                           b[ni >> 1][(ni & 1) * 2], b[ni >> 1][(ni & 1) * 2 + 1]);
        }
    }

    // Epilogue: dequant, exp(sim - margin), per-row reduce
    float sbv[8][2];
    {
        const int colb = ntile * TN + wn * 64 + ((lane & 3) << 1);
        #pragma unroll
        for (int ni = 0; ni < 8; ni++) {
            sbv[ni][0] = __ldg(&g_sclT[colb + ni * 8]);
            sbv[ni][1] = __ldg(&g_sclT[colb + ni * 8 + 1]);
        }
    }
    #pragma unroll
    for (int mi = 0; mi < 4; mi++) {
        const int rlo = mtile * TM + wm * 64 + mi * 16 + (lane >> 2);
        const float sa0 = __ldg(&g_sclI[rlo]);
        const float sa1 = __ldg(&g_sclI[rlo + 8]);
        float s0 = 0.0f, s1 = 0.0f;
        #pragma unroll
        for (int ni = 0; ni < 8; ni++) {
            s0 += __expf(__int2float_rn(acc[mi][ni][0]) * sa0 * sbv[ni][0] - MARGINF)
                + __expf(__int2float_rn(acc[mi][ni][1]) * sa0 * sbv[ni][1] - MARGINF);
            s1 += __expf(__int2float_rn(acc[mi][ni][2]) * sa1 * sbv[ni][0] - MARGINF)
                + __expf(__int2float_rn(acc[mi][ni][3]) * sa1 * sbv[ni][1] - MARGINF);
        }
        s0 += __shfl_xor_sync(0xffffffffu, s0, 1);
        s0 += __shfl_xor_sync(0xffffffffu, s0, 2);
        s1 += __shfl_xor_sync(0xffffffffu, s1, 1);
        s1 += __shfl_xor_sync(0xffffffffu, s1, 2);
        if ((lane & 3) == 0) {
            const int r = wm * 64 + mi * 16 + (lane >> 2);
            atomicAdd(&rowAcc[r], s0);
            atomicAdd(&rowAcc[r + 8], s1);
        }
    }
    __syncthreads();
    if (tid < TM)
        g_partial[(size_t)ntile * NROW + mtile * TM + tid] = rowAcc[tid];

    if (tid == 0) {
        #pragma unroll
        for (int s = 0; s < STAGES; s++) mbar_inval(fullb + 8u * s);
    }
}

// ---------------------------------------------------------------------------
// Kernel 3a: per-row lse = log(sum of NTN partials) - pos
// ---------------------------------------------------------------------------
__global__ void finalize1_kernel() {
    const int row = blockIdx.x * 256 + threadIdx.x;
    float s = 0.0f;
    #pragma unroll
    for (int p = 0; p < NTN; p++) s += g_partial[(size_t)p * NROW + row];
    g_lse[row] = logf(s) - g_pos[row];
}

// ---------------------------------------------------------------------------
// Kernel 3b: mean over rows
// ---------------------------------------------------------------------------
__global__ void finalize2_kernel(float* __restrict__ out) {
    __shared__ float red[256];
    float s = 0.0f;
    for (int i = threadIdx.x; i < NROW; i += 256) s += g_lse[i];
    red[threadIdx.x] = s;
    __syncthreads();
    #pragma unroll
    for (int off = 128; off > 0; off >>= 1) {
        if (threadIdx.x < off) red[threadIdx.x] += red[threadIdx.x + off];
        __syncthreads();
    }
    if (threadIdx.x == 0) out[0] = red[0] / (float)NROW;
}

// ---------------------------------------------------------------------------
extern "C" void kernel_launch(void* const* d_in, const int* in_sizes, int n_in,
                              void* d_out, int out_size) {
    const float* img = (const float*)d_in[0];
    const float* txt = (const float*)d_in[1];
    float* out = (float*)d_out;

    norm_kernel<<<NROW, 256>>>(img, txt);

    cudaFuncSetAttribute(gemm_lse_kernel,
                         cudaFuncAttributeMaxDynamicSharedMemorySize,
                         STAGES * STG_BYTES + 128);
    dim3 grid(NTM, NTN);
    gemm_lse_kernel<<<grid, 256, STAGES * STG_BYTES + 128>>>();

    finalize1_kernel<<<NROW / 256, 256>>>();
    finalize2_kernel<<<1, 256>>>(out);
}

// round 6
// speedup vs baseline: 3.2359x; 3.2359x over previous
#include <cuda_runtime.h>
#include <cuda_bf16.h>
#include <cstdint>

#define NROW 8192
#define DDIM 1024
#define CH 64                     // K per pipeline chunk (64 bf16 = 128 B)
#define KCH (DDIM / CH)           // 16 chunks
#define STAGES 4
#define TM 128                    // CTA tile M
#define TN 256                    // CTA tile N
#define NTM (NROW / TM)           // 64
#define NTN (NROW / TN)           // 32
#define STG_A (TM * 128)          // 16 KB
#define STG_B (TN * 128)          // 32 KB
#define STG_BYTES (STG_A + STG_B) // 48 KB
#define CHUNK_STRIDE ((size_t)NROW * 128)  // 1 MB per k-chunk blob
#define MARGINF 1.0f

// ---------------- device scratch ----------------
__device__ __nv_bfloat16 g_imgn[(size_t)NROW * DDIM];  // chunk-major swizzled, 16 MB
__device__ __nv_bfloat16 g_txtn[(size_t)NROW * DDIM];  // chunk-major swizzled, 16 MB
__device__ float g_pos[NROW];
__device__ float g_partial[(size_t)NTN * NROW];        // [ntile][row]
__device__ float g_lse[NROW];

// ---------------- PTX helpers ----------------
__device__ __forceinline__ uint32_t smem_u32(const void* p) {
    uint32_t a;
    asm("{ .reg .u64 t; cvta.to.shared.u64 t, %1; cvt.u32.u64 %0, t; }" : "=r"(a) : "l"(p));
    return a;
}
__device__ __forceinline__ void mbar_init(uint32_t a, uint32_t c) {
    asm volatile("mbarrier.init.shared.b64 [%0], %1;" :: "r"(a), "r"(c) : "memory");
}
__device__ __forceinline__ void mbar_inval(uint32_t a) {
    asm volatile("mbarrier.inval.shared.b64 [%0];" :: "r"(a) : "memory");
}
__device__ __forceinline__ void mbar_expect_tx(uint32_t a, uint32_t tx) {
    asm volatile("mbarrier.arrive.expect_tx.shared.b64 _, [%0], %1;" :: "r"(a), "r"(tx) : "memory");
}
__device__ __forceinline__ void mbar_arrive(uint32_t a) {
    asm volatile("mbarrier.arrive.shared.b64 _, [%0];" :: "r"(a) : "memory");
}
__device__ __forceinline__ void mbar_wait(uint32_t a, uint32_t parity) {
    asm volatile(
        "{\n\t.reg .pred P;\n\t"
        "WL_%=:\n\t"
        "mbarrier.try_wait.parity.shared.b64 P, [%0], %1;\n\t"
        "@!P bra WL_%=;\n\t}"
        :: "r"(a), "r"(parity) : "memory");
}
__device__ __forceinline__ void bulk_g2s(uint32_t dst, const void* src, uint32_t bytes, uint32_t mbar) {
    asm volatile(
        "cp.async.bulk.shared::cluster.global.mbarrier::complete_tx::bytes [%0], [%1], %2, [%3];"
        :: "r"(dst), "l"(src), "r"(bytes), "r"(mbar) : "memory");
}
__device__ __forceinline__ void ldsm_x4(uint32_t& r0, uint32_t& r1, uint32_t& r2, uint32_t& r3,
                                        uint32_t addr) {
    asm volatile("ldmatrix.sync.aligned.m8n8.x4.shared.b16 {%0,%1,%2,%3}, [%4];"
                 : "=r"(r0), "=r"(r1), "=r"(r2), "=r"(r3) : "r"(addr));
}
__device__ __forceinline__ void mma16816(float& c0, float& c1, float& c2, float& c3,
                                         uint32_t a0, uint32_t a1, uint32_t a2, uint32_t a3,
                                         uint32_t b0, uint32_t b1) {
    asm volatile(
        "mma.sync.aligned.m16n8k16.row.col.f32.bf16.bf16.f32 "
        "{%0,%1,%2,%3}, {%4,%5,%6,%7}, {%8,%9}, {%0,%1,%2,%3};"
        : "+f"(c0), "+f"(c1), "+f"(c2), "+f"(c3)
        : "r"(a0), "r"(a1), "r"(a2), "r"(a3), "r"(b0), "r"(b1));
}

// ---------------------------------------------------------------------------
// Kernel 1: L2-normalize -> bf16, chunk-major + XOR-swizzled layout, fp32 pos.
// ---------------------------------------------------------------------------
__global__ void norm_kernel(const float* __restrict__ img,
                            const float* __restrict__ txt) {
    const int row = blockIdx.x;
    const int t = threadIdx.x;

    const float4 a = reinterpret_cast<const float4*>(img + (size_t)row * DDIM)[t];
    const float4 b = reinterpret_cast<const float4*>(txt + (size_t)row * DDIM)[t];

    float sii = a.x * a.x + a.y * a.y + a.z * a.z + a.w * a.w;
    float stt = b.x * b.x + b.y * b.y + b.z * b.z + b.w * b.w;
    float sit = a.x * b.x + a.y * b.y + a.z * b.z + a.w * b.w;

    #pragma unroll
    for (int o = 16; o; o >>= 1) {
        sii += __shfl_xor_sync(0xffffffffu, sii, o);
        stt += __shfl_xor_sync(0xffffffffu, stt, o);
        sit += __shfl_xor_sync(0xffffffffu, sit, o);
    }

    __shared__ float w0[8], w1[8], w2[8], bc[3];
    if ((t & 31) == 0) { w0[t >> 5] = sii; w1[t >> 5] = stt; w2[t >> 5] = sit; }
    __syncthreads();
    if (t == 0) {
        float a0 = 0.f, a1 = 0.f, a2 = 0.f;
        #pragma unroll
        for (int i = 0; i < 8; i++) { a0 += w0[i]; a1 += w1[i]; a2 += w2[i]; }
        bc[0] = a0; bc[1] = a1; bc[2] = a2;
    }
    __syncthreads();

    const float inv_i = 1.0f / fmaxf(sqrtf(bc[0]), 1e-12f);
    const float inv_t = 1.0f / fmaxf(sqrtf(bc[1]), 1e-12f);

    __nv_bfloat162 i01 = __floats2bfloat162_rn(a.x * inv_i, a.y * inv_i);
    __nv_bfloat162 i23 = __floats2bfloat162_rn(a.z * inv_i, a.w * inv_i);
    __nv_bfloat162 t01 = __floats2bfloat162_rn(b.x * inv_t, b.y * inv_t);
    __nv_bfloat162 t23 = __floats2bfloat162_rn(b.z * inv_t, b.w * inv_t);

    uint2 pi, pt;
    pi.x = *reinterpret_cast<unsigned int*>(&i01);
    pi.y = *reinterpret_cast<unsigned int*>(&i23);
    pt.x = *reinterpret_cast<unsigned int*>(&t01);
    pt.y = *reinterpret_cast<unsigned int*>(&t23);

    const int c = t >> 4;                // k-chunk (64 cols each)
    const int ci = (t & 15) << 2;        // col within chunk (4 bf16)
    uint32_t off = (uint32_t)row * 128u + (uint32_t)ci * 2u;
    off ^= (off >> 3) & 0x70u;
    const size_t addr = (size_t)c * CHUNK_STRIDE + off;

    *reinterpret_cast<uint2*>(reinterpret_cast<char*>(g_imgn) + addr) = pi;
    *reinterpret_cast<uint2*>(reinterpret_cast<char*>(g_txtn) + addr) = pt;

    if (t == 0) g_pos[row] = bc[2] * inv_i * inv_t;  // exact fp32 diagonal
}

// ---------------------------------------------------------------------------
// Kernel 2: bulk-async 4-stage mma.sync bf16 GEMM + fused exp(sim-1) rowsum.
// CTA tile 128x256, 8 warps = 2(m) x 4(n), warp tile 64x64.
// Full/empty mbarrier ring per slot -- NO per-chunk __syncthreads.
// ---------------------------------------------------------------------------
__global__ __launch_bounds__(256, 1) void gemm_lse_kernel() {
    extern __shared__ __align__(128) char smem[];       // STAGES*48KB (+pad)
    __shared__ __align__(8) unsigned long long full_bar[STAGES], empty_bar[STAGES];
    __shared__ float rowAcc[TM];

    const int tid = threadIdx.x;
    const int warp = tid >> 5;
    const int lane = tid & 31;
    const int wm = warp >> 2;        // 0..1
    const int wn = warp & 3;         // 0..3
    const int mtile = blockIdx.x;    // 64
    const int ntile = blockIdx.y;    // 32

    uint32_t sbase = smem_u32(smem);
    sbase = (sbase + 127u) & ~127u;
    const uint32_t fullb = smem_u32(&full_bar[0]);
    const uint32_t emptyb = smem_u32(&empty_bar[0]);

    if (tid == 0) {
        #pragma unroll
        for (int s = 0; s < STAGES; s++) {
            mbar_init(fullb + 8u * s, 1);
            mbar_init(emptyb + 8u * s, 8);   // one arrive per warp
        }
    }
    if (tid < TM) rowAcc[tid] = 0.0f;
    __syncthreads();

    const char* baseA = reinterpret_cast<const char*>(g_imgn) + (size_t)mtile * STG_A;
    const char* baseB = reinterpret_cast<const char*>(g_txtn) + (size_t)ntile * STG_B;

    // prologue: chunks 0..STAGES-2 into slots 0..2
    if (tid == 0) {
        #pragma unroll
        for (int c = 0; c < STAGES - 1; c++) {
            const uint32_t st = sbase + (uint32_t)c * STG_BYTES;
            mbar_expect_tx(fullb + 8u * c, STG_BYTES);
            bulk_g2s(st,         baseA + (size_t)c * CHUNK_STRIDE, STG_A, fullb + 8u * c);
            bulk_g2s(st + STG_A, baseB + (size_t)c * CHUNK_STRIDE, STG_B, fullb + 8u * c);
        }
    }

    float acc[4][8][4];
    #pragma unroll
    for (int mi = 0; mi < 4; mi++)
        #pragma unroll
        for (int ni = 0; ni < 8; ni++)
            #pragma unroll
            for (int e = 0; e < 4; e++) acc[mi][ni][e] = 0.0f;

    #pragma unroll 4
    for (int c = 0; c < KCH; c++) {
        const int s = c & (STAGES - 1);
        mbar_wait(fullb + 8u * s, (uint32_t)((c >> 2) & 1));

        const uint32_t sa = sbase + (uint32_t)s * STG_BYTES;
        const uint32_t sb = sa + STG_A;

        #pragma unroll
        for (int ks = 0; ks < 4; ks++) {
            uint32_t a[4][4], b[4][4];
            #pragma unroll
            for (int mi = 0; mi < 4; mi++) {
                const int r = wm * 64 + mi * 16 + (lane & 15);
                const int g = 2 * ks + (lane >> 4);
                ldsm_x4(a[mi][0], a[mi][1], a[mi][2], a[mi][3],
                        sa + (uint32_t)r * 128u + (uint32_t)((g ^ (r & 7)) << 4));
            }
            #pragma unroll
            for (int bi = 0; bi < 4; bi++) {
                const int nr = wn * 64 + bi * 16 + (lane & 7) + ((lane >> 4) << 3);
                const int g = 2 * ks + ((lane >> 3) & 1);
                ldsm_x4(b[bi][0], b[bi][1], b[bi][2], b[bi][3],
                        sb + (uint32_t)nr * 128u + (uint32_t)((g ^ (nr & 7)) << 4));
            }
            #pragma unroll
            for (int mi = 0; mi < 4; mi++)
                #pragma unroll
                for (int ni = 0; ni < 8; ni++)
                    mma16816(acc[mi][ni][0], acc[mi][ni][1], acc[mi][ni][2], acc[mi][ni][3],
                             a[mi][0], a[mi][1], a[mi][2], a[mi][3],
                             b[ni >> 1][(ni & 1) * 2], b[ni >> 1][(ni & 1) * 2 + 1]);
        }

        // this warp is done consuming slot s for chunk c
        if (lane == 0) mbar_arrive(emptyb + 8u * s);

        // producer: issue chunk c+STAGES-1 (slot was consumed at chunk c-1)
        if (tid == 0) {
            const int nx = c + STAGES - 1;
            if (nx < KCH) {
                const int sn = nx & (STAGES - 1);
                if (nx >= STAGES)
                    mbar_wait(emptyb + 8u * sn, (uint32_t)(((nx >> 2) - 1) & 1));
                const uint32_t st = sbase + (uint32_t)sn * STG_BYTES;
                mbar_expect_tx(fullb + 8u * sn, STG_BYTES);
                bulk_g2s(st,         baseA + (size_t)nx * CHUNK_STRIDE, STG_A, fullb + 8u * sn);
                bulk_g2s(st + STG_A, baseB + (size_t)nx * CHUNK_STRIDE, STG_B, fullb + 8u * sn);
            }
        }
    }

    // Epilogue: exp(sim - margin), per-row reduce (quad shfl + smem atomics)
    #pragma unroll
    for (int mi = 0; mi < 4; mi++) {
        float s0 = 0.0f, s1 = 0.0f;
        #pragma unroll
        for (int ni = 0; ni < 8; ni++) {
            s0 += __expf(acc[mi][ni][0] - MARGINF) + __expf(acc[mi][ni][1] - MARGINF);
            s1 += __expf(acc[mi][ni][2] - MARGINF) + __expf(acc[mi][ni][3] - MARGINF);
        }
        s0 += __shfl_xor_sync(0xffffffffu, s0, 1);
        s0 += __shfl_xor_sync(0xffffffffu, s0, 2);
        s1 += __shfl_xor_sync(0xffffffffu, s1, 1);
        s1 += __shfl_xor_sync(0xffffffffu, s1, 2);
        if ((lane & 3) == 0) {
            const int r = wm * 64 + mi * 16 + (lane >> 2);
            atomicAdd(&rowAcc[r], s0);
            atomicAdd(&rowAcc[r + 8], s1);
        }
    }
    __syncthreads();
    if (tid < TM)
        g_partial[(size_t)ntile * NROW + mtile * TM + tid] = rowAcc[tid];

    if (tid == 0) {
        #pragma unroll
        for (int s = 0; s < STAGES; s++) {
            mbar_inval(fullb + 8u * s);
            mbar_inval(emptyb + 8u * s);
        }
    }
}

// ---------------------------------------------------------------------------
// Kernel 3a: per-row lse = log(sum of NTN partials) - pos
// ---------------------------------------------------------------------------
__global__ void finalize1_kernel() {
    const int row = blockIdx.x * 256 + threadIdx.x;
    float s = 0.0f;
    #pragma unroll
    for (int p = 0; p < NTN; p++) s += g_partial[(size_t)p * NROW + row];
    g_lse[row] = logf(s) - g_pos[row];
}

// ---------------------------------------------------------------------------
// Kernel 3b: mean over rows (1024 threads, fixed-order tree)
// ---------------------------------------------------------------------------
__global__ void finalize2_kernel(float* __restrict__ out) {
    __shared__ float red[1024];
    float s = 0.0f;
    #pragma unroll
    for (int i = 0; i < NROW / 1024; i++) s += g_lse[threadIdx.x + i * 1024];
    red[threadIdx.x] = s;
    __syncthreads();
    #pragma unroll
    for (int off = 512; off > 0; off >>= 1) {
        if (threadIdx.x < off) red[threadIdx.x] += red[threadIdx.x + off];
        __syncthreads();
    }
    if (threadIdx.x == 0) out[0] = red[0] / (float)NROW;
}

// ---------------------------------------------------------------------------
extern "C" void kernel_launch(void* const* d_in, const int* in_sizes, int n_in,
                              void* d_out, int out_size) {
    const float* img = (const float*)d_in[0];
    const float* txt = (const float*)d_in[1];
    float* out = (float*)d_out;

    norm_kernel<<<NROW, 256>>>(img, txt);

    cudaFuncSetAttribute(gemm_lse_kernel,
                         cudaFuncAttributeMaxDynamicSharedMemorySize,
                         STAGES * STG_BYTES + 128);
    dim3 grid(NTM, NTN);
    gemm_lse_kernel<<<grid, 256, STAGES * STG_BYTES + 128>>>();

    finalize1_kernel<<<NROW / 256, 256>>>();
    finalize2_kernel<<<1, 1024>>>(out);
}